// round 11
// baseline (speedup 1.0000x reference)
#include <cuda_runtime.h>

// QLSTM collapsed analytically:
//   quantum_gate(comb, p)[:, k] = prod_{j<=k} cos(p_j) * cos(comb_j)
// Only k < H=4 used; comb[0:4] = x  => gates depend only on x_t.
// Per (b,k): c = f*c + i*g ; h = o*tanh(c); gate args in [-1,1].
//
// Chassis: warp = 2 batch els x QUARTER of T (32 steps); CHUNK=2;
//   block = 4 warps = 4 quarters of one b-pair. NEW THIS ROUND:
//   - grid = 1024 blocks, each does 2 consecutive b-pair tiles -> all blocks
//     resident simultaneously (<= 8/SM x 148 = 1184): ZERO wave tail.
//   - prep kernel precomputes the 16 param prefix-products (no per-thread
//     param LDG/cos prologue).
//   - p54 tanh for output (|c| <= ~1.3 in practice; validated passing).

#define T_STEPS 128
#define BATCH   4096
#define CHUNK   2
#define FULLMASK 0xffffffffu

__device__ float g_A[16];   // [AFh x4, AIh x4, AG x4, AOh x4]

__global__ void qlstm_prep(const float* __restrict__ pf_,
                           const float* __restrict__ pi_,
                           const float* __restrict__ pg_,
                           const float* __restrict__ po_) {
    if (threadIdx.x == 0) {
        float f = 1.f, i = 1.f, g = 1.f, o = 1.f;
#pragma unroll
        for (int j = 0; j < 4; ++j) {
            f *= cosf(pf_[j]); i *= cosf(pi_[j]);
            g *= cosf(pg_[j]); o *= cosf(po_[j]);
            g_A[j]      = 0.5f * f;   // sigmoid poly takes arg/2
            g_A[4 + j]  = 0.5f * i;
            g_A[8 + j]  = g;
            g_A[12 + j] = 0.5f * o;
        }
    }
}

// sigmoid(2u), |u|<=0.5 : 0.5 + u*q(u^2); tanh Taylor deg-9 halved, err ~2e-6
__device__ __forceinline__ float sig_poly(float u) {
    float w = u * u;
    float q = fmaf(w, fmaf(w, fmaf(w, fmaf(w, 0.010934744f,
                                              -0.026984127f),
                                       0.066666667f),
                               -0.166666667f),
                       0.5f);
    return fmaf(u, q, 0.5f);
}
// tanh Pade(5,4); err ~4e-8 at |z|<=1, ~5e-7 at |z|<=1.3
__device__ __forceinline__ float tanh_p54(float z) {
    float w = z * z;
    float n = z * fmaf(w, fmaf(w, 1.0f, 105.0f), 945.0f);
    float d =     fmaf(w, fmaf(w, 15.0f, 420.0f), 945.0f);
    return __fdividef(n, d);
}

__global__ void __launch_bounds__(128, 8) qlstm_kernel(
    const float* __restrict__ inp,   // [T, B, 4]
    float* __restrict__ out)         // [T*B*4 + B*4 + B*4]
{
    const int quarter = threadIdx.x >> 5;    // 0..3 : which quarter of T
    const int lane    = threadIdx.x & 31;
    const int bsub    = lane & 1;
    const int chunk   = lane >> 1;           // 0..15
    const int t0q     = quarter * 32 + chunk * CHUNK;

    // per-tile quarter totals: affine map per (tile, quarter, bsub) over k
    __shared__ float4 sF[2][4][2];
    __shared__ float4 sC[2][4][2];

    // precomputed param prefix products
    const float4 AF = ((const float4*)g_A)[0];
    const float4 AI = ((const float4*)g_A)[1];
    const float4 AG = ((const float4*)g_A)[2];
    const float4 AO = ((const float4*)g_A)[3];

    const float4* __restrict__ xin = (const float4*)inp;
    float4* __restrict__ out4 = (float4*)out;

#pragma unroll
    for (int tile = 0; tile < 2; ++tile) {
        const int b = (blockIdx.x * 2 + tile) * 2 + bsub;

        // ---- pass 1: load once, cache gates, accumulate chunk affine map ----
        float Fc[CHUNK][4], Gc[CHUNK][4], Oc[CHUNK][4];
        float cl0 = 0.f, cl1 = 0.f, cl2 = 0.f, cl3 = 0.f;
        float pf0 = 1.f, pf1 = 1.f, pf2 = 1.f, pf3 = 1.f;

#pragma unroll
        for (int it = 0; it < CHUNK; ++it) {
            float4 x = xin[(t0q + it) * BATCH + b];
            float P0 = __cosf(x.x);
            float P1 = P0 * __cosf(x.y);
            float P2 = P1 * __cosf(x.z);
            float P3 = P2 * __cosf(x.w);

            float f, i, g, ig;
            f = sig_poly(AF.x * P0); i = sig_poly(AI.x * P0); g = tanh_p54(AG.x * P0);
            ig = i * g; Fc[it][0] = f; Gc[it][0] = ig; Oc[it][0] = sig_poly(AO.x * P0);
            cl0 = fmaf(f, cl0, ig); pf0 *= f;

            f = sig_poly(AF.y * P1); i = sig_poly(AI.y * P1); g = tanh_p54(AG.y * P1);
            ig = i * g; Fc[it][1] = f; Gc[it][1] = ig; Oc[it][1] = sig_poly(AO.y * P1);
            cl1 = fmaf(f, cl1, ig); pf1 *= f;

            f = sig_poly(AF.z * P2); i = sig_poly(AI.z * P2); g = tanh_p54(AG.z * P2);
            ig = i * g; Fc[it][2] = f; Gc[it][2] = ig; Oc[it][2] = sig_poly(AO.z * P2);
            cl2 = fmaf(f, cl2, ig); pf2 *= f;

            f = sig_poly(AF.w * P3); i = sig_poly(AI.w * P3); g = tanh_p54(AG.w * P3);
            ig = i * g; Fc[it][3] = f; Gc[it][3] = ig; Oc[it][3] = sig_poly(AO.w * P3);
            cl3 = fmaf(f, cl3, ig); pf3 *= f;
        }

        // ---- scan over 16 chunks (lanes stride 2, same bsub) ----
        float F0 = pf0, C0 = cl0, F1 = pf1, C1 = cl1;
        float F2 = pf2, C2 = cl2, F3 = pf3, C3 = cl3;
#pragma unroll
        for (int off = 1; off <= 8; off <<= 1) {
            const int ol = off * 2;
            float Fo0 = __shfl_up_sync(FULLMASK, F0, ol), Co0 = __shfl_up_sync(FULLMASK, C0, ol);
            float Fo1 = __shfl_up_sync(FULLMASK, F1, ol), Co1 = __shfl_up_sync(FULLMASK, C1, ol);
            float Fo2 = __shfl_up_sync(FULLMASK, F2, ol), Co2 = __shfl_up_sync(FULLMASK, C2, ol);
            float Fo3 = __shfl_up_sync(FULLMASK, F3, ol), Co3 = __shfl_up_sync(FULLMASK, C3, ol);
            if (chunk >= off) {
                C0 = fmaf(F0, Co0, C0); F0 *= Fo0;
                C1 = fmaf(F1, Co1, C1); F1 *= Fo1;
                C2 = fmaf(F2, Co2, C2); F2 *= Fo2;
                C3 = fmaf(F3, Co3, C3); F3 *= Fo3;
            }
        }

        // publish this quarter's total affine map (chunk 15 inclusive)
        if (chunk == 15) {
            sF[tile][quarter][bsub] = make_float4(F0, F1, F2, F3);
            sC[tile][quarter][bsub] = make_float4(C0, C1, C2, C3);
        }

        // exclusive prefix within this quarter
        float Fe0 = __shfl_up_sync(FULLMASK, F0, 2), Ce0 = __shfl_up_sync(FULLMASK, C0, 2);
        float Fe1 = __shfl_up_sync(FULLMASK, F1, 2), Ce1 = __shfl_up_sync(FULLMASK, C1, 2);
        float Fe2 = __shfl_up_sync(FULLMASK, F2, 2), Ce2 = __shfl_up_sync(FULLMASK, C2, 2);
        float Fe3 = __shfl_up_sync(FULLMASK, F3, 2), Ce3 = __shfl_up_sync(FULLMASK, C3, 2);
        if (chunk == 0) {
            Fe0 = 1.f; Ce0 = 0.f; Fe1 = 1.f; Ce1 = 0.f;
            Fe2 = 1.f; Ce2 = 0.f; Fe3 = 1.f; Ce3 = 0.f;
        }

        __syncthreads();

        // fold preceding quarters' maps: c = C_q + F_q * c
        float ch0 = 0.f, ch1 = 0.f, ch2 = 0.f, ch3 = 0.f;
#pragma unroll
        for (int q = 0; q < 3; ++q) {
            if (quarter > q) {
                float4 Fq = sF[tile][q][bsub];
                float4 Cq = sC[tile][q][bsub];
                ch0 = fmaf(Fq.x, ch0, Cq.x);
                ch1 = fmaf(Fq.y, ch1, Cq.y);
                ch2 = fmaf(Fq.z, ch2, Cq.z);
                ch3 = fmaf(Fq.w, ch3, Cq.w);
            }
        }

        float c0 = fmaf(Fe0, ch0, Ce0);
        float c1 = fmaf(Fe1, ch1, Ce1);
        float c2 = fmaf(Fe2, ch2, Ce2);
        float c3 = fmaf(Fe3, ch3, Ce3);

        // ---- pass 2: pure-register recurrence, emit h ----
        float h0 = 0.f, h1 = 0.f, h2 = 0.f, h3 = 0.f;
#pragma unroll
        for (int it = 0; it < CHUNK; ++it) {
            c0 = fmaf(Fc[it][0], c0, Gc[it][0]);
            c1 = fmaf(Fc[it][1], c1, Gc[it][1]);
            c2 = fmaf(Fc[it][2], c2, Gc[it][2]);
            c3 = fmaf(Fc[it][3], c3, Gc[it][3]);

            h0 = Oc[it][0] * tanh_p54(c0);
            h1 = Oc[it][1] * tanh_p54(c1);
            h2 = Oc[it][2] * tanh_p54(c2);
            h3 = Oc[it][3] * tanh_p54(c3);

            __stcs(&out4[(t0q + it) * BATCH + b], make_float4(h0, h1, h2, h3));
        }

        // final state: quarter 3, chunk 15, it = CHUNK-1 (t = 127)
        if (quarter == 3 && chunk == 15) {
            out4[T_STEPS * BATCH + b]         = make_float4(h0, h1, h2, h3); // hx
            out4[T_STEPS * BATCH + BATCH + b] = make_float4(c0, c1, c2, c3); // cx
        }
    }
}

extern "C" void kernel_launch(void* const* d_in, const int* in_sizes, int n_in,
                              void* d_out, int out_size) {
    (void)in_sizes; (void)n_in; (void)out_size;
    const float* inp   = (const float*)d_in[0];
    const float* prm_f = (const float*)d_in[1];
    const float* prm_i = (const float*)d_in[2];
    const float* prm_g = (const float*)d_in[3];
    const float* prm_o = (const float*)d_in[4];
    float* out = (float*)d_out;

    qlstm_prep<<<1, 32>>>(prm_f, prm_i, prm_g, prm_o);
    // 1024 blocks x 2 sequential b-pair tiles: every block resident at once
    // (<= 8 blocks/SM x 148 SMs), no trailing wave.
    qlstm_kernel<<<1024, 128>>>(inp, out);
}

// round 12
// speedup vs baseline: 1.3459x; 1.3459x over previous
#include <cuda_runtime.h>

// QLSTM collapsed analytically:
//   quantum_gate(comb, p)[:, k] = prod_{j<=k} cos(p_j) * cos(comb_j)
// Only k < H=4 used; comb[0:4] = x  => gates depend only on x_t.
// Per (b,k): c = f*c + i*g ; h = o*tanh(c); gate args in [-1,1].
//
// Chassis (round 9, best): warp = 2 batch els x QUARTER of T; CHUNK=2;
//   lane = (chunk 0..15)*2 + bsub; block = 4 warps = 4 quarters of one b-pair;
//   grid = 2048 blocks; quarters linked by smem affine fold.
// This round: cooperative 16-lane param prologue via smem (kills per-thread
//   16x LDG + 16x cos), economized deg-7 sigmoid, p54 output tanh,
//   closed-form 2-step chunk aggregates. Single kernel (no prep launch).

#define T_STEPS 128
#define BATCH   4096
#define CHUNK   2
#define FULLMASK 0xffffffffu

// sigmoid(2u), |u|<=0.5 : 0.5 + u*q(w), w=u^2; deg-7 economized (== deg-9
// Taylor to ~3e-7 over the range)
__device__ __forceinline__ float sig_poly(float u) {
    float w = u * u;
    float q = fmaf(w, fmaf(w, fmaf(w, -0.0215166f,
                                       0.0658124f),
                               -0.1666240f),
                       0.4999997f);
    return fmaf(u, q, 0.5f);
}
// tanh Pade(5,4); err ~4e-8 at |z|<=1, ~5e-7 at |z|<=1.3
__device__ __forceinline__ float tanh_p54(float z) {
    float w = z * z;
    float n = z * fmaf(w, fmaf(w, 1.0f, 105.0f), 945.0f);
    float d =     fmaf(w, fmaf(w, 15.0f, 420.0f), 945.0f);
    return __fdividef(n, d);
}

__global__ void __launch_bounds__(128, 8) qlstm_kernel(
    const float* __restrict__ inp,   // [T, B, 4]
    const float* __restrict__ prm_f, // [8]
    const float* __restrict__ prm_i,
    const float* __restrict__ prm_g,
    const float* __restrict__ prm_o,
    float* __restrict__ out)         // [T*B*4 + B*4 + B*4]
{
    const int tid     = threadIdx.x;
    const int quarter = tid >> 5;            // 0..3 : which quarter of T
    const int lane    = tid & 31;
    const int bsub    = lane & 1;
    const int chunk   = lane >> 1;           // 0..15
    const int b       = blockIdx.x * 2 + bsub;
    const int t0      = quarter * 32 + chunk * CHUNK;

    // quarter totals: affine map (F_tot, C_tot) per (quarter, bsub, k0..3)
    __shared__ float4 sF[4][2];
    __shared__ float4 sC[4][2];
    __shared__ float4 sA[4];   // AFh, AIh, AG, AOh (float4 over k)

    const float4* __restrict__ xin = (const float4*)inp;

    // prefetch this thread's inputs BEFORE the prologue sync (hides LDG latency)
    float4 x0 = xin[(t0 + 0) * BATCH + b];
    float4 x1 = xin[(t0 + 1) * BATCH + b];

    // cooperative param prologue: lanes 0..15 of warp 0, gate = tid>>2, j = tid&3
    if (tid < 16) {
        const int j = tid & 3;
        const float* p = (tid < 8) ? ((tid < 4) ? prm_f : prm_i)
                                   : ((tid < 12) ? prm_g : prm_o);
        float v = __cosf(p[j]);
        // prefix product within each 4-lane gate group (width=4 segments)
        float s1 = __shfl_up_sync(0xffffu, v, 1, 4);
        if (j >= 1) v *= s1;
        float s2 = __shfl_up_sync(0xffffu, v, 2, 4);
        if (j >= 2) v *= s2;
        // sigmoid gates prescaled by 0.5 (sig_poly takes arg/2); AG (tid 8..11) not
        float scale = (tid >= 8 && tid < 12) ? 1.0f : 0.5f;
        ((float*)sA)[tid] = scale * v;
    }
    __syncthreads();

    const float4 AF = sA[0], AI = sA[1], AG = sA[2], AO = sA[3];

    // ---- pass 1: compute & cache gates for the 2 steps ----
    float Fc[CHUNK][4], Gc[CHUNK][4], Oc[CHUNK][4];
#pragma unroll
    for (int it = 0; it < CHUNK; ++it) {
        float4 x = (it == 0) ? x0 : x1;
        float P0 = __cosf(x.x);
        float P1 = P0 * __cosf(x.y);
        float P2 = P1 * __cosf(x.z);
        float P3 = P2 * __cosf(x.w);

        Fc[it][0] = sig_poly(AF.x * P0);
        Fc[it][1] = sig_poly(AF.y * P1);
        Fc[it][2] = sig_poly(AF.z * P2);
        Fc[it][3] = sig_poly(AF.w * P3);
        Gc[it][0] = sig_poly(AI.x * P0) * tanh_p54(AG.x * P0);
        Gc[it][1] = sig_poly(AI.y * P1) * tanh_p54(AG.y * P1);
        Gc[it][2] = sig_poly(AI.z * P2) * tanh_p54(AG.z * P2);
        Gc[it][3] = sig_poly(AI.w * P3) * tanh_p54(AG.w * P3);
        Oc[it][0] = sig_poly(AO.x * P0);
        Oc[it][1] = sig_poly(AO.y * P1);
        Oc[it][2] = sig_poly(AO.z * P2);
        Oc[it][3] = sig_poly(AO.w * P3);
    }

    // closed-form 2-step chunk aggregates: F = f1*f0, C = f1*ig0 + ig1
    float F0 = Fc[1][0] * Fc[0][0], C0 = fmaf(Fc[1][0], Gc[0][0], Gc[1][0]);
    float F1 = Fc[1][1] * Fc[0][1], C1 = fmaf(Fc[1][1], Gc[0][1], Gc[1][1]);
    float F2 = Fc[1][2] * Fc[0][2], C2 = fmaf(Fc[1][2], Gc[0][2], Gc[1][2]);
    float F3 = Fc[1][3] * Fc[0][3], C3 = fmaf(Fc[1][3], Gc[0][3], Gc[1][3]);

    // ---- scan over 16 chunks (lanes stride 2, same bsub) ----
#pragma unroll
    for (int off = 1; off <= 8; off <<= 1) {
        const int ol = off * 2;
        float Fo0 = __shfl_up_sync(FULLMASK, F0, ol), Co0 = __shfl_up_sync(FULLMASK, C0, ol);
        float Fo1 = __shfl_up_sync(FULLMASK, F1, ol), Co1 = __shfl_up_sync(FULLMASK, C1, ol);
        float Fo2 = __shfl_up_sync(FULLMASK, F2, ol), Co2 = __shfl_up_sync(FULLMASK, C2, ol);
        float Fo3 = __shfl_up_sync(FULLMASK, F3, ol), Co3 = __shfl_up_sync(FULLMASK, C3, ol);
        if (chunk >= off) {
            C0 = fmaf(F0, Co0, C0); F0 *= Fo0;
            C1 = fmaf(F1, Co1, C1); F1 *= Fo1;
            C2 = fmaf(F2, Co2, C2); F2 *= Fo2;
            C3 = fmaf(F3, Co3, C3); F3 *= Fo3;
        }
    }

    // publish this quarter's total affine map (chunk 15 inclusive values)
    if (chunk == 15) {
        sF[quarter][bsub] = make_float4(F0, F1, F2, F3);
        sC[quarter][bsub] = make_float4(C0, C1, C2, C3);
    }

    // exclusive prefix within this quarter
    float Fe0 = __shfl_up_sync(FULLMASK, F0, 2), Ce0 = __shfl_up_sync(FULLMASK, C0, 2);
    float Fe1 = __shfl_up_sync(FULLMASK, F1, 2), Ce1 = __shfl_up_sync(FULLMASK, C1, 2);
    float Fe2 = __shfl_up_sync(FULLMASK, F2, 2), Ce2 = __shfl_up_sync(FULLMASK, C2, 2);
    float Fe3 = __shfl_up_sync(FULLMASK, F3, 2), Ce3 = __shfl_up_sync(FULLMASK, C3, 2);
    if (chunk == 0) {
        Fe0 = 1.f; Ce0 = 0.f; Fe1 = 1.f; Ce1 = 0.f;
        Fe2 = 1.f; Ce2 = 0.f; Fe3 = 1.f; Ce3 = 0.f;
    }

    __syncthreads();

    // fold preceding quarters' maps: c = C_q + F_q * c, q = 0..quarter-1
    float ch0 = 0.f, ch1 = 0.f, ch2 = 0.f, ch3 = 0.f;
#pragma unroll
    for (int q = 0; q < 3; ++q) {
        if (quarter > q) {
            float4 Fq = sF[q][bsub];
            float4 Cq = sC[q][bsub];
            ch0 = fmaf(Fq.x, ch0, Cq.x);
            ch1 = fmaf(Fq.y, ch1, Cq.y);
            ch2 = fmaf(Fq.z, ch2, Cq.z);
            ch3 = fmaf(Fq.w, ch3, Cq.w);
        }
    }

    float c0 = fmaf(Fe0, ch0, Ce0);
    float c1 = fmaf(Fe1, ch1, Ce1);
    float c2 = fmaf(Fe2, ch2, Ce2);
    float c3 = fmaf(Fe3, ch3, Ce3);

    // ---- pass 2: pure-register recurrence, emit h ----
    float4* __restrict__ out4 = (float4*)out;
    float h0 = 0.f, h1 = 0.f, h2 = 0.f, h3 = 0.f;

#pragma unroll
    for (int it = 0; it < CHUNK; ++it) {
        c0 = fmaf(Fc[it][0], c0, Gc[it][0]);
        c1 = fmaf(Fc[it][1], c1, Gc[it][1]);
        c2 = fmaf(Fc[it][2], c2, Gc[it][2]);
        c3 = fmaf(Fc[it][3], c3, Gc[it][3]);

        h0 = Oc[it][0] * tanh_p54(c0);   // |c| <= ~1.3 -> p54 err ~5e-7
        h1 = Oc[it][1] * tanh_p54(c1);
        h2 = Oc[it][2] * tanh_p54(c2);
        h3 = Oc[it][3] * tanh_p54(c3);

        __stcs(&out4[(t0 + it) * BATCH + b], make_float4(h0, h1, h2, h3));
    }

    // final state: quarter 3, chunk 15, it = CHUNK-1 (t = 127)
    if (quarter == 3 && chunk == 15) {
        out4[T_STEPS * BATCH + b]         = make_float4(h0, h1, h2, h3); // hx
        out4[T_STEPS * BATCH + BATCH + b] = make_float4(c0, c1, c2, c3); // cx
    }
}

extern "C" void kernel_launch(void* const* d_in, const int* in_sizes, int n_in,
                              void* d_out, int out_size) {
    (void)in_sizes; (void)n_in; (void)out_size;
    const float* inp   = (const float*)d_in[0];
    const float* prm_f = (const float*)d_in[1];
    const float* prm_i = (const float*)d_in[2];
    const float* prm_g = (const float*)d_in[3];
    const float* prm_o = (const float*)d_in[4];
    float* out = (float*)d_out;

    // 8192 warps: block = 4 quarters of one b-pair -> 2048 blocks, 1 launch
    qlstm_kernel<<<2048, 128>>>(inp, prm_f, prm_i, prm_g, prm_o, out);
}

// round 13
// speedup vs baseline: 1.3780x; 1.0238x over previous
#include <cuda_runtime.h>

// QLSTM collapsed analytically:
//   quantum_gate(comb, p)[:, k] = prod_{j<=k} cos(p_j) * cos(comb_j)
// Only k < H=4 used; comb[0:4] = x  => gates depend only on x_t.
// Per (b,k): c = f*c + i*g ; h = o*tanh(c); gate args in [-1,1].
//
// Mapping (this round): warp = 4 batch els x 16 t-steps; CHUNK=2;
//   lane = (chunk 0..7)*4 + bsub(0..3)  -> each 4-lane group reads/writes
//   64B contiguous per t-row: 8 L1 lines per LDG/STG (was 16).
//   Block = 8 warps = 8 t-segments of one 4-b group (256 thr, grid 1024).
//   Warp scan (3 rounds) over 8 chunks; segments linked via smem affine fold.
// Math identical to round 12 (deg-7 sigmoid, p54 tanh) - validated 2.6e-7.

#define T_STEPS 128
#define BATCH   4096
#define CHUNK   2
#define FULLMASK 0xffffffffu

// sigmoid(2u), |u|<=0.5 : 0.5 + u*q(w), w=u^2; deg-7 economized
__device__ __forceinline__ float sig_poly(float u) {
    float w = u * u;
    float q = fmaf(w, fmaf(w, fmaf(w, -0.0215166f,
                                       0.0658124f),
                               -0.1666240f),
                       0.4999997f);
    return fmaf(u, q, 0.5f);
}
// tanh Pade(5,4); err ~4e-8 at |z|<=1, ~2e-5 at |z|<=2.1
__device__ __forceinline__ float tanh_p54(float z) {
    float w = z * z;
    float n = z * fmaf(w, fmaf(w, 1.0f, 105.0f), 945.0f);
    float d =     fmaf(w, fmaf(w, 15.0f, 420.0f), 945.0f);
    return __fdividef(n, d);
}

__global__ void __launch_bounds__(256, 4) qlstm_kernel(
    const float* __restrict__ inp,   // [T, B, 4]
    const float* __restrict__ prm_f, // [8]
    const float* __restrict__ prm_i,
    const float* __restrict__ prm_g,
    const float* __restrict__ prm_o,
    float* __restrict__ out)         // [T*B*4 + B*4 + B*4]
{
    const int tid   = threadIdx.x;
    const int seg   = tid >> 5;              // 0..7 : 16-step t-segment
    const int lane  = tid & 31;
    const int bsub  = lane & 3;              // 0..3
    const int chunk = lane >> 2;             // 0..7 (2 steps each)
    const int b     = blockIdx.x * 4 + bsub;
    const int t0    = seg * 16 + chunk * CHUNK;

    // segment totals: affine map per (seg, bsub) over k
    __shared__ float4 sF[8][4];
    __shared__ float4 sC[8][4];
    __shared__ float4 sA[4];   // AFh, AIh, AG, AOh (float4 over k)

    const float4* __restrict__ xin = (const float4*)inp;

    // prefetch inputs BEFORE the prologue sync (hides LDG latency)
    float4 x0 = xin[(t0 + 0) * BATCH + b];
    float4 x1 = xin[(t0 + 1) * BATCH + b];

    // cooperative param prologue: threads 0..15; gate = tid>>2, j = tid&3
    if (tid < 16) {
        const int j = tid & 3;
        const float* p = (tid < 8) ? ((tid < 4) ? prm_f : prm_i)
                                   : ((tid < 12) ? prm_g : prm_o);
        float v = __cosf(p[j]);
        float s1 = __shfl_up_sync(0xffffu, v, 1, 4);
        if (j >= 1) v *= s1;
        float s2 = __shfl_up_sync(0xffffu, v, 2, 4);
        if (j >= 2) v *= s2;
        float scale = (tid >= 8 && tid < 12) ? 1.0f : 0.5f;  // AG unscaled
        ((float*)sA)[tid] = scale * v;
    }
    __syncthreads();

    const float4 AF = sA[0], AI = sA[1], AG = sA[2], AO = sA[3];

    // ---- pass 1: compute & cache gates for the 2 steps ----
    float Fc[CHUNK][4], Gc[CHUNK][4], Oc[CHUNK][4];
#pragma unroll
    for (int it = 0; it < CHUNK; ++it) {
        float4 x = (it == 0) ? x0 : x1;
        float P0 = __cosf(x.x);
        float P1 = P0 * __cosf(x.y);
        float P2 = P1 * __cosf(x.z);
        float P3 = P2 * __cosf(x.w);

        Fc[it][0] = sig_poly(AF.x * P0);
        Fc[it][1] = sig_poly(AF.y * P1);
        Fc[it][2] = sig_poly(AF.z * P2);
        Fc[it][3] = sig_poly(AF.w * P3);
        Gc[it][0] = sig_poly(AI.x * P0) * tanh_p54(AG.x * P0);
        Gc[it][1] = sig_poly(AI.y * P1) * tanh_p54(AG.y * P1);
        Gc[it][2] = sig_poly(AI.z * P2) * tanh_p54(AG.z * P2);
        Gc[it][3] = sig_poly(AI.w * P3) * tanh_p54(AG.w * P3);
        Oc[it][0] = sig_poly(AO.x * P0);
        Oc[it][1] = sig_poly(AO.y * P1);
        Oc[it][2] = sig_poly(AO.z * P2);
        Oc[it][3] = sig_poly(AO.w * P3);
    }

    // closed-form 2-step chunk aggregates: F = f1*f0, C = f1*ig0 + ig1
    float F0 = Fc[1][0] * Fc[0][0], C0 = fmaf(Fc[1][0], Gc[0][0], Gc[1][0]);
    float F1 = Fc[1][1] * Fc[0][1], C1 = fmaf(Fc[1][1], Gc[0][1], Gc[1][1]);
    float F2 = Fc[1][2] * Fc[0][2], C2 = fmaf(Fc[1][2], Gc[0][2], Gc[1][2]);
    float F3 = Fc[1][3] * Fc[0][3], C3 = fmaf(Fc[1][3], Gc[0][3], Gc[1][3]);

    // ---- scan over 8 chunks (lanes stride 4, same bsub): 3 rounds ----
#pragma unroll
    for (int off = 1; off <= 4; off <<= 1) {
        const int ol = off * 4;
        float Fo0 = __shfl_up_sync(FULLMASK, F0, ol), Co0 = __shfl_up_sync(FULLMASK, C0, ol);
        float Fo1 = __shfl_up_sync(FULLMASK, F1, ol), Co1 = __shfl_up_sync(FULLMASK, C1, ol);
        float Fo2 = __shfl_up_sync(FULLMASK, F2, ol), Co2 = __shfl_up_sync(FULLMASK, C2, ol);
        float Fo3 = __shfl_up_sync(FULLMASK, F3, ol), Co3 = __shfl_up_sync(FULLMASK, C3, ol);
        if (chunk >= off) {
            C0 = fmaf(F0, Co0, C0); F0 *= Fo0;
            C1 = fmaf(F1, Co1, C1); F1 *= Fo1;
            C2 = fmaf(F2, Co2, C2); F2 *= Fo2;
            C3 = fmaf(F3, Co3, C3); F3 *= Fo3;
        }
    }

    // publish this segment's total affine map (chunk 7 = inclusive total)
    if (chunk == 7) {
        sF[seg][bsub] = make_float4(F0, F1, F2, F3);
        sC[seg][bsub] = make_float4(C0, C1, C2, C3);
    }

    // exclusive prefix within this segment (shift by one chunk = 4 lanes)
    float Fe0 = __shfl_up_sync(FULLMASK, F0, 4), Ce0 = __shfl_up_sync(FULLMASK, C0, 4);
    float Fe1 = __shfl_up_sync(FULLMASK, F1, 4), Ce1 = __shfl_up_sync(FULLMASK, C1, 4);
    float Fe2 = __shfl_up_sync(FULLMASK, F2, 4), Ce2 = __shfl_up_sync(FULLMASK, C2, 4);
    float Fe3 = __shfl_up_sync(FULLMASK, F3, 4), Ce3 = __shfl_up_sync(FULLMASK, C3, 4);
    if (chunk == 0) {
        Fe0 = 1.f; Ce0 = 0.f; Fe1 = 1.f; Ce1 = 0.f;
        Fe2 = 1.f; Ce2 = 0.f; Fe3 = 1.f; Ce3 = 0.f;
    }

    __syncthreads();

    // fold preceding segments' maps (ascending): c = C_q + F_q * c
    float ch0 = 0.f, ch1 = 0.f, ch2 = 0.f, ch3 = 0.f;
#pragma unroll
    for (int q = 0; q < 7; ++q) {
        if (seg > q) {               // uniform per warp
            float4 Fq = sF[q][bsub];
            float4 Cq = sC[q][bsub];
            ch0 = fmaf(Fq.x, ch0, Cq.x);
            ch1 = fmaf(Fq.y, ch1, Cq.y);
            ch2 = fmaf(Fq.z, ch2, Cq.z);
            ch3 = fmaf(Fq.w, ch3, Cq.w);
        }
    }

    float c0 = fmaf(Fe0, ch0, Ce0);
    float c1 = fmaf(Fe1, ch1, Ce1);
    float c2 = fmaf(Fe2, ch2, Ce2);
    float c3 = fmaf(Fe3, ch3, Ce3);

    // ---- pass 2: pure-register recurrence, emit h ----
    float4* __restrict__ out4 = (float4*)out;
    float h0 = 0.f, h1 = 0.f, h2 = 0.f, h3 = 0.f;

#pragma unroll
    for (int it = 0; it < CHUNK; ++it) {
        c0 = fmaf(Fc[it][0], c0, Gc[it][0]);
        c1 = fmaf(Fc[it][1], c1, Gc[it][1]);
        c2 = fmaf(Fc[it][2], c2, Gc[it][2]);
        c3 = fmaf(Fc[it][3], c3, Gc[it][3]);

        h0 = Oc[it][0] * tanh_p54(c0);
        h1 = Oc[it][1] * tanh_p54(c1);
        h2 = Oc[it][2] * tanh_p54(c2);
        h3 = Oc[it][3] * tanh_p54(c3);

        __stcs(&out4[(t0 + it) * BATCH + b], make_float4(h0, h1, h2, h3));
    }

    // final state: seg 7, chunk 7, it = CHUNK-1 (t = 127)
    if (seg == 7 && chunk == 7) {
        out4[T_STEPS * BATCH + b]         = make_float4(h0, h1, h2, h3); // hx
        out4[T_STEPS * BATCH + BATCH + b] = make_float4(c0, c1, c2, c3); // cx
    }
}

extern "C" void kernel_launch(void* const* d_in, const int* in_sizes, int n_in,
                              void* d_out, int out_size) {
    (void)in_sizes; (void)n_in; (void)out_size;
    const float* inp   = (const float*)d_in[0];
    const float* prm_f = (const float*)d_in[1];
    const float* prm_i = (const float*)d_in[2];
    const float* prm_g = (const float*)d_in[3];
    const float* prm_o = (const float*)d_in[4];
    float* out = (float*)d_out;

    // 8192 warps: block = 8 t-segments of one 4-b group -> 1024 blocks
    qlstm_kernel<<<1024, 256>>>(inp, prm_f, prm_i, prm_g, prm_o, out);
}

// round 14
// speedup vs baseline: 1.3821x; 1.0030x over previous
#include <cuda_runtime.h>

// QLSTM collapsed analytically:
//   quantum_gate(comb, p)[:, k] = prod_{j<=k} cos(p_j) * cos(comb_j)
// Only k < H=4 used; comb[0:4] = x  => gates depend only on x_t.
// Per (b,k): c = f*c + i*g ; h = o*tanh(c); gate args in [-1,1], |c| <= 2.1.
//
// Chassis = round 7 (best ncu, fewest instructions): warp = 2 b x HALF of T;
//   lane = (chunk 0..15)*2 + bsub; CHUNK=4; block = 4 warps = (pair x half);
//   halves linked via smem; 4096 warps, grid 1024.
// This round: smem param prologue, p54 output tanh, 72-reg cap for occupancy.

#define T_STEPS 128
#define BATCH   4096
#define CHUNK   4
#define FULLMASK 0xffffffffu

// sigmoid(2u), |u|<=0.5 : 0.5 + u*q(w), w=u^2; deg-7 economized, err ~3e-7
__device__ __forceinline__ float sig_poly(float u) {
    float w = u * u;
    float q = fmaf(w, fmaf(w, fmaf(w, -0.0215166f,
                                       0.0658124f),
                               -0.1666240f),
                       0.4999997f);
    return fmaf(u, q, 0.5f);
}
// tanh Pade(5,4); err ~4e-8 at |z|<=1, ~3e-5 at |z|<=2.1
__device__ __forceinline__ float tanh_p54(float z) {
    float w = z * z;
    float n = z * fmaf(w, fmaf(w, 1.0f, 105.0f), 945.0f);
    float d =     fmaf(w, fmaf(w, 15.0f, 420.0f), 945.0f);
    return __fdividef(n, d);
}

__global__ void __launch_bounds__(128, 7) qlstm_kernel(
    const float* __restrict__ inp,   // [T, B, 4]
    const float* __restrict__ prm_f, // [8]
    const float* __restrict__ prm_i,
    const float* __restrict__ prm_g,
    const float* __restrict__ prm_o,
    float* __restrict__ out)         // [T*B*4 + B*4 + B*4]
{
    const int tid   = threadIdx.x;
    const int wid   = tid >> 5;              // 0..3
    const int lane  = tid & 31;
    const int half  = wid & 1;               // t-half: 0 -> t<64, 1 -> t>=64
    const int pair  = wid >> 1;              // b-pair within block
    const int bsub  = lane & 1;
    const int chunk = lane >> 1;             // 0..15
    const int b     = blockIdx.x * 4 + pair * 2 + bsub;
    const int t0    = half * 64 + chunk * CHUNK;

    // smem: half-0's total c at t=63 per (pair, bsub, k); param products
    __shared__ float sC[2][2][4];
    __shared__ float4 sA[4];   // AFh, AIh, AG, AOh (float4 over k)

    const float4* __restrict__ xin = (const float4*)inp;

    // prefetch all 4 inputs BEFORE the prologue sync (hides DRAM latency)
    float4 xs0 = xin[(t0 + 0) * BATCH + b];
    float4 xs1 = xin[(t0 + 1) * BATCH + b];
    float4 xs2 = xin[(t0 + 2) * BATCH + b];
    float4 xs3 = xin[(t0 + 3) * BATCH + b];

    // cooperative param prologue: threads 0..15 (warp 0); gate = tid>>2, j = tid&3
    if (tid < 16) {
        const int j = tid & 3;
        const float* p = (tid < 8) ? ((tid < 4) ? prm_f : prm_i)
                                   : ((tid < 12) ? prm_g : prm_o);
        float v = __cosf(p[j]);
        float s1 = __shfl_up_sync(0xffffu, v, 1, 4);
        if (j >= 1) v *= s1;
        float s2 = __shfl_up_sync(0xffffu, v, 2, 4);
        if (j >= 2) v *= s2;
        float scale = (tid >= 8 && tid < 12) ? 1.0f : 0.5f;  // AG unscaled
        ((float*)sA)[tid] = scale * v;
    }
    __syncthreads();

    const float4 AF = sA[0], AI = sA[1], AG = sA[2], AO = sA[3];

    // ---- pass 1: cache gates, accumulate chunk affine map ----
    float Fc[CHUNK][4], Gc[CHUNK][4], Oc[CHUNK][4];
    float cl0 = 0.f, cl1 = 0.f, cl2 = 0.f, cl3 = 0.f;
    float pf0 = 1.f, pf1 = 1.f, pf2 = 1.f, pf3 = 1.f;

#pragma unroll
    for (int it = 0; it < CHUNK; ++it) {
        float4 x = (it == 0) ? xs0 : (it == 1) ? xs1 : (it == 2) ? xs2 : xs3;
        float P0 = __cosf(x.x);
        float P1 = P0 * __cosf(x.y);
        float P2 = P1 * __cosf(x.z);
        float P3 = P2 * __cosf(x.w);

        float f, ig;
        f = sig_poly(AF.x * P0); ig = sig_poly(AI.x * P0) * tanh_p54(AG.x * P0);
        Fc[it][0] = f; Gc[it][0] = ig; Oc[it][0] = sig_poly(AO.x * P0);
        cl0 = fmaf(f, cl0, ig); pf0 *= f;

        f = sig_poly(AF.y * P1); ig = sig_poly(AI.y * P1) * tanh_p54(AG.y * P1);
        Fc[it][1] = f; Gc[it][1] = ig; Oc[it][1] = sig_poly(AO.y * P1);
        cl1 = fmaf(f, cl1, ig); pf1 *= f;

        f = sig_poly(AF.z * P2); ig = sig_poly(AI.z * P2) * tanh_p54(AG.z * P2);
        Fc[it][2] = f; Gc[it][2] = ig; Oc[it][2] = sig_poly(AO.z * P2);
        cl2 = fmaf(f, cl2, ig); pf2 *= f;

        f = sig_poly(AF.w * P3); ig = sig_poly(AI.w * P3) * tanh_p54(AG.w * P3);
        Fc[it][3] = f; Gc[it][3] = ig; Oc[it][3] = sig_poly(AO.w * P3);
        cl3 = fmaf(f, cl3, ig); pf3 *= f;
    }

    // ---- scan over 16 chunks (lanes stride 2, same bsub) ----
    float F0 = pf0, C0 = cl0, F1 = pf1, C1 = cl1;
    float F2 = pf2, C2 = cl2, F3 = pf3, C3 = cl3;
#pragma unroll
    for (int off = 1; off <= 8; off <<= 1) {
        const int ol = off * 2;
        float Fo0 = __shfl_up_sync(FULLMASK, F0, ol), Co0 = __shfl_up_sync(FULLMASK, C0, ol);
        float Fo1 = __shfl_up_sync(FULLMASK, F1, ol), Co1 = __shfl_up_sync(FULLMASK, C1, ol);
        float Fo2 = __shfl_up_sync(FULLMASK, F2, ol), Co2 = __shfl_up_sync(FULLMASK, C2, ol);
        float Fo3 = __shfl_up_sync(FULLMASK, F3, ol), Co3 = __shfl_up_sync(FULLMASK, C3, ol);
        if (chunk >= off) {
            C0 = fmaf(F0, Co0, C0); F0 *= Fo0;
            C1 = fmaf(F1, Co1, C1); F1 *= Fo1;
            C2 = fmaf(F2, Co2, C2); F2 *= Fo2;
            C3 = fmaf(F3, Co3, C3); F3 *= Fo3;
        }
    }

    // half-0 publishes total c at t=63 (chunk 15 inclusive, c_in = 0)
    if (half == 0 && chunk == 15) {
        sC[pair][bsub][0] = C0;
        sC[pair][bsub][1] = C1;
        sC[pair][bsub][2] = C2;
        sC[pair][bsub][3] = C3;
    }

    // exclusive prefix within this half
    float Fe0 = __shfl_up_sync(FULLMASK, F0, 2), Ce0 = __shfl_up_sync(FULLMASK, C0, 2);
    float Fe1 = __shfl_up_sync(FULLMASK, F1, 2), Ce1 = __shfl_up_sync(FULLMASK, C1, 2);
    float Fe2 = __shfl_up_sync(FULLMASK, F2, 2), Ce2 = __shfl_up_sync(FULLMASK, C2, 2);
    float Fe3 = __shfl_up_sync(FULLMASK, F3, 2), Ce3 = __shfl_up_sync(FULLMASK, C3, 2);
    if (chunk == 0) {
        Fe0 = 1.f; Ce0 = 0.f; Fe1 = 1.f; Ce1 = 0.f;
        Fe2 = 1.f; Ce2 = 0.f; Fe3 = 1.f; Ce3 = 0.f;
    }

    __syncthreads();

    // incoming c for this half (0 for half 0; half-0's total for half 1)
    float ch0 = 0.f, ch1 = 0.f, ch2 = 0.f, ch3 = 0.f;
    if (half == 1) {
        ch0 = sC[pair][bsub][0];
        ch1 = sC[pair][bsub][1];
        ch2 = sC[pair][bsub][2];
        ch3 = sC[pair][bsub][3];
    }

    float c0 = fmaf(Fe0, ch0, Ce0);
    float c1 = fmaf(Fe1, ch1, Ce1);
    float c2 = fmaf(Fe2, ch2, Ce2);
    float c3 = fmaf(Fe3, ch3, Ce3);

    // ---- pass 2: pure-register recurrence, emit h ----
    float4* __restrict__ out4 = (float4*)out;
    float h0 = 0.f, h1 = 0.f, h2 = 0.f, h3 = 0.f;

#pragma unroll
    for (int it = 0; it < CHUNK; ++it) {
        c0 = fmaf(Fc[it][0], c0, Gc[it][0]);
        c1 = fmaf(Fc[it][1], c1, Gc[it][1]);
        c2 = fmaf(Fc[it][2], c2, Gc[it][2]);
        c3 = fmaf(Fc[it][3], c3, Gc[it][3]);

        h0 = Oc[it][0] * tanh_p54(c0);
        h1 = Oc[it][1] * tanh_p54(c1);
        h2 = Oc[it][2] * tanh_p54(c2);
        h3 = Oc[it][3] * tanh_p54(c3);

        __stcs(&out4[(t0 + it) * BATCH + b], make_float4(h0, h1, h2, h3));
    }

    // final state from half 1, chunk 15, it=3 (t = 127)
    if (half == 1 && chunk == 15) {
        out4[T_STEPS * BATCH + b]         = make_float4(h0, h1, h2, h3); // hx
        out4[T_STEPS * BATCH + BATCH + b] = make_float4(c0, c1, c2, c3); // cx
    }
}

extern "C" void kernel_launch(void* const* d_in, const int* in_sizes, int n_in,
                              void* d_out, int out_size) {
    (void)in_sizes; (void)n_in; (void)out_size;
    const float* inp   = (const float*)d_in[0];
    const float* prm_f = (const float*)d_in[1];
    const float* prm_i = (const float*)d_in[2];
    const float* prm_g = (const float*)d_in[3];
    const float* prm_o = (const float*)d_in[4];
    float* out = (float*)d_out;

    // 4096 warps: 2 b x half-T per warp; 4 warps/block -> 1024 blocks
    qlstm_kernel<<<1024, 128>>>(inp, prm_f, prm_i, prm_g, prm_o, out);
}